// round 8
// baseline (speedup 1.0000x reference)
#include <cuda_runtime.h>
#include <cuda_fp16.h>
#include <cstdint>
#include <math.h>

#define CIN   64
#define COUT  128
#define HH    224
#define WW    224
#define OH    222
#define OW    222

#define TPX    32          // output px per tile (x)
#define TROWS  4           // output rows per tile (y)
#define INROWS 6           // staged input rows = TROWS + 2
#define PXST   34          // staged px per row = TPX + 2
#define SLAB_STRIDE 5120   // bytes per input row slab (multiple of 1024)

#define NTX 7              // tiles in x
#define NTY 56             // tiles in y
#define NTILES (NTX * NTY * 16)   // 6272
#define GRID_PERSIST 296   // 2 CTAs/SM x 148 SMs

// ---------------- global scratch ----------------
// fp16 transposed input: [b][y][px][ci], 16*224*224*64 halfs (~103MB)
__device__ __half g_xh[(size_t)16 * HH * WW * CIN];
// a-fragment-shuffled fp16 weights: [tap(9)][ks(4)][mblk(8)][lane(32)] x uint4
__device__ uint4 g_Wfrag[9 * 4 * 8 * 32];

__global__ void prep_w(const float* __restrict__ w) {
    int i = blockIdx.x * 256 + threadIdx.x;
    if (i >= 9216) return;
    int lane = i & 31;
    int mblk = (i >> 5) & 7;
    int q    = i >> 8;            // tap*4 + ks
    int ks   = q & 3;
    int tap  = q >> 2;
    int kh = tap / 3, kw = tap - kh * 3;

    int r  = lane >> 2;
    int k0 = ks * 16 + (lane & 3) * 2;

    uint32_t words[4];
#pragma unroll
    for (int wi = 0; wi < 4; wi++) {
        int co = mblk * 16 + r + (wi & 1) * 8;
        int kk = k0 + (wi >> 1) * 8;
        uint32_t packed = 0;
#pragma unroll
        for (int j = 0; j < 2; j++) {
            float v = w[((co * CIN + (kk + j)) * 3 + kh) * 3 + kw];
            packed |= (uint32_t)__half_as_ushort(__float2half(v)) << (16 * j);
        }
        words[wi] = packed;
    }
    g_Wfrag[i] = make_uint4(words[0], words[1], words[2], words[3]);
}

// ---- transpose+convert: x[b][ci][y][px] fp32 -> g_xh[b][y][px][ci] fp16 ----
#define TSTR 72   // smem half-stride per px row (144B, 16B-aligned)
__global__ __launch_bounds__(256)
void prep_x(const float* __restrict__ x) {
    __shared__ __half sT[64 * TSTR];   // [px(64)][ci(64)] halfs
    const int b   = blockIdx.z;
    const int y   = blockIdx.y;
    const int px0 = blockIdx.x * 64;
    const int t   = threadIdx.x;
    const int wid = t >> 5, lane = t & 31;

    const int px = (wid & 1) * 32 + lane;
    const int ip = px0 + px;
    const bool okx = ip < WW;
    const int cib = wid >> 1;          // 0..3
#pragma unroll
    for (int k = 0; k < 16; k++) {
        int ci = cib + k * 4;
        float v = okx ? __ldg(&x[(((size_t)b * CIN + ci) * HH + y) * WW + ip]) : 0.0f;
        sT[px * TSTR + ci] = __float2half(v);
    }
    __syncthreads();

    for (int c = t; c < 512; c += 256) {      // 64 px * 8 cig chunks of 16B
        int pxw = c >> 3, cig = c & 7;
        int ipw = px0 + pxw;
        if (ipw < WW) {
            uint4 val = *(const uint4*)&sT[pxw * TSTR + cig * 8];
            *(uint4*)((char*)g_xh + (((size_t)(b * HH + y) * WW + ipw) << 7) + (cig << 4)) = val;
        }
    }
}

// ---------------- helpers ----------------
__device__ __forceinline__ uint32_t smem_u32(const void* p) {
    uint32_t a;
    asm("{ .reg .u64 t; cvta.to.shared.u64 t, %1; cvt.u32.u64 %0, t; }" : "=r"(a) : "l"(p));
    return a;
}
__device__ __forceinline__ uint32_t swz(uint32_t off) { return off ^ ((off >> 3) & 0x70); }

__device__ __forceinline__ void ldsm4(uint32_t& r0, uint32_t& r1, uint32_t& r2, uint32_t& r3, uint32_t addr) {
    asm volatile("ldmatrix.sync.aligned.m8n8.x4.shared.b16 {%0, %1, %2, %3}, [%4];"
        : "=r"(r0), "=r"(r1), "=r"(r2), "=r"(r3) : "r"(addr));
}
__device__ __forceinline__ void mma16816(float* d, const uint4& a, uint32_t b0, uint32_t b1) {
    asm volatile("mma.sync.aligned.m16n8k16.row.col.f32.f16.f16.f32 "
        "{%0, %1, %2, %3}, {%4, %5, %6, %7}, {%8, %9}, {%0, %1, %2, %3};"
        : "+f"(d[0]), "+f"(d[1]), "+f"(d[2]), "+f"(d[3])
        : "r"(a.x), "r"(a.y), "r"(a.z), "r"(a.w), "r"(b0), "r"(b1));
}
__device__ __forceinline__ void cp16(uint32_t dst, const void* src, int sz) {
    asm volatile("cp.async.cg.shared.global [%0], [%1], 16, %2;"
        :: "r"(dst), "l"(src), "r"(sz) : "memory");
}

#define BUF_BYTES (INROWS * SLAB_STRIDE)          // 30720
#define OFF_MIN   (2 * BUF_BYTES)                 // 61440
#define SMEM_BYTES (OFF_MIN + 1024 + 1024)        // 63488

// stage tile t's 6 input rows into buffer at bufbase (cp.async, 1 commit group)
__device__ __forceinline__ void stage_tile(int t, uint32_t bufbase, int tid) {
    int bx  = t % NTX;
    int rem = t / NTX;
    int by  = rem % NTY;
    int bb  = rem / NTY;
    int x0s  = bx * TPX;
    int oy0s = by * TROWS;
#pragma unroll 1
    for (int c = tid; c < INROWS * PXST * 8; c += 256) {   // 1632 chunks
        int cig = c & 7;
        int q   = c >> 3;            // 0..203
        int px  = q % PXST;
        int g   = q / PXST;
        int y   = oy0s + g;
        int ix  = x0s + px;
        bool ok = (y < HH) && (ix < WW);
        const char* src = (const char*)g_xh +
            (ok ? ((((size_t)(bb * HH + y) * WW + ix) << 7) + ((size_t)cig << 4)) : 0);
        uint32_t dst = bufbase + (uint32_t)(g * SLAB_STRIDE)
                     + (uint32_t)(px * 128 + ((cig ^ (px & 7)) << 4));
        cp16(dst, src, ok ? 16 : 0);
    }
    asm volatile("cp.async.commit_group;" ::: "memory");
}

__global__ __launch_bounds__(256, 2)
void conv_mma_kernel(const float* __restrict__ bias,
                     float* __restrict__ out) {
    extern __shared__ char smem_raw[];
    uint32_t sb = (smem_u32(smem_raw) + 1023u) & ~1023u;

    const int tid  = threadIdx.x;
    const int wid  = tid >> 5;
    const int lane = tid & 31;

    const int warpM = wid & 1;       // co half: 64*warpM .. +63
    const int warpN = wid >> 1;      // output row within tile: 0..3

    // per-thread bias values (constant across tiles)
    float bias0[4], bias1[4];
#pragma unroll
    for (int m = 0; m < 4; m++) {
        int r_co = warpM * 64 + m * 16 + (lane >> 2);
        bias0[m] = __ldg(&bias[r_co]);
        bias1[m] = __ldg(&bias[r_co + 8]);
    }

    const uint4* gw = g_Wfrag;
    const int rowpx   = (lane & 7) + ((lane >> 4) << 3);   // 0..15
    const int kb_lane = ((lane >> 3) & 1) * 16;
    const int awoff   = warpM * 4;
    float* sMin = (float*)(smem_raw + (sb - smem_u32(smem_raw)) + OFF_MIN);  // [2][128]

    int buf = 0;
    int t0 = blockIdx.x;
    stage_tile(t0, sb, tid);    // first tile into buffer 0

    for (int t = t0; t < NTILES; t += GRID_PERSIST) {
        // wait for current tile's staging (overlapped with previous tile's MMAs)
        asm volatile("cp.async.wait_group 0;" ::: "memory");
        __syncthreads();

        // prefetch next tile into the other buffer
        int tn = t + GRID_PERSIST;
        if (tn < NTILES) stage_tile(tn, sb + (buf ^ 1) * BUF_BYTES, tid);

        const uint32_t bufbase = sb + buf * BUF_BYTES;

        // ---- accumulators, init = bias[co] ----
        float acc[4][4][4];
#pragma unroll
        for (int m = 0; m < 4; m++) {
#pragma unroll
            for (int f = 0; f < 4; f++) {
                acc[m][f][0] = bias0[m]; acc[m][f][1] = bias0[m];
                acc[m][f][2] = bias1[m]; acc[m][f][3] = bias1[m];
            }
        }

#pragma unroll
        for (int kh = 0; kh < 3; kh++) {
            const uint32_t slab = bufbase + (uint32_t)((warpN + kh) * SLAB_STRIDE);
#pragma unroll
            for (int kw = 0; kw < 3; kw++) {
                const int tap = kh * 3 + kw;
#pragma unroll
                for (int ks = 0; ks < 4; ks++) {
                    uint4 A[4];
                    const int base = (tap * 4 + ks) * 8;
#pragma unroll
                    for (int m = 0; m < 4; m++)
                        A[m] = __ldg(&gw[(base + awoff + m) * 32 + lane]);

                    uint32_t B[8];
#pragma unroll
                    for (int half = 0; half < 2; half++) {
                        uint32_t off = swz((uint32_t)((rowpx + half * 16 + kw) * 128 + kb_lane + ks * 32));
                        ldsm4(B[half*4+0], B[half*4+1], B[half*4+2], B[half*4+3], slab + off);
                    }
#pragma unroll
                    for (int m = 0; m < 4; m++) {
#pragma unroll
                        for (int f = 0; f < 4; f++)
                            mma16816(acc[m][f], A[m], B[f*2], B[f*2+1]);
                    }
                }
            }
        }

        // ---- epilogue: min over co ----
#pragma unroll
        for (int f = 0; f < 4; f++) {
            float v0 = __int_as_float(0x7f800000), v1 = v0;
#pragma unroll
            for (int m = 0; m < 4; m++) {
                v0 = fminf(v0, fminf(acc[m][f][0], acc[m][f][2]));
                v1 = fminf(v1, fminf(acc[m][f][1], acc[m][f][3]));
            }
#pragma unroll
            for (int off = 4; off < 32; off <<= 1) {
                v0 = fminf(v0, __shfl_xor_sync(0xffffffffu, v0, off));
                v1 = fminf(v1, __shfl_xor_sync(0xffffffffu, v1, off));
            }
            if ((lane >> 2) == 0) {
                int px = (f >> 1) * 16 + (f & 1) * 8 + (lane & 3) * 2;  // 0..31 within row
                int idx = warpN * TPX + px;
                sMin[warpM * 128 + idx]     = v0;
                sMin[warpM * 128 + idx + 1] = v1;
            }
        }
        __syncthreads();

        if (tid < 128) {
            int bx  = t % NTX;
            int rem = t / NTX;
            int by  = rem % NTY;
            int bb  = rem / NTY;
            int r = tid >> 5, c = tid & 31;
            int orow = by * TROWS + r, ocol = bx * TPX + c;
            if (orow < OH && ocol < OW) {
                float m = fminf(sMin[tid], sMin[128 + tid]);
                out[((size_t)bb * OH + orow) * OW + ocol] = tanhf(tanhf(m));
            }
        }
        buf ^= 1;
        // next iteration's wait_group+sync orders sMin reuse and buffer swap
    }
}

extern "C" void kernel_launch(void* const* d_in, const int* in_sizes, int n_in,
                              void* d_out, int out_size) {
    const float* x    = (const float*)d_in[0];
    const float* w    = (const float*)d_in[1];
    const float* bias = (const float*)d_in[2];
    float* out = (float*)d_out;

    prep_w<<<(9216 + 255) / 256, 256>>>(w);
    prep_x<<<dim3(4, HH, 16), 256>>>(x);

    cudaFuncSetAttribute(conv_mma_kernel, cudaFuncAttributeMaxDynamicSharedMemorySize, SMEM_BYTES);
    conv_mma_kernel<<<GRID_PERSIST, 256, SMEM_BYTES>>>(bias, out);
}

// round 9
// speedup vs baseline: 1.0615x; 1.0615x over previous
#include <cuda_runtime.h>
#include <cuda_fp16.h>
#include <cstdint>
#include <math.h>

#define CIN   64
#define COUT  128
#define HH    224
#define WW    224
#define OH    222
#define OW    222

#define TPX    32          // output px per tile (x)
#define TROWS  4           // output rows per tile (y)
#define INROWS 6           // staged input rows = TROWS + 2
#define PXST   34          // staged px per row = TPX + 2
#define SLAB_STRIDE 5120   // bytes per input row slab (multiple of 1024)

// ---------------- global scratch ----------------
// fp16 transposed input: [b][y][px][ci], 16*224*224*64 halfs (~103MB)
__device__ __half g_xh[(size_t)16 * HH * WW * CIN];
// a-fragment-shuffled fp16 weights: [tap(9)][ks(4)][mblk(8)][lane(32)] x uint4
__device__ uint4 g_Wfrag[9 * 4 * 8 * 32];

__global__ void prep_w(const float* __restrict__ w) {
    int i = blockIdx.x * 256 + threadIdx.x;
    if (i >= 9216) return;
    int lane = i & 31;
    int mblk = (i >> 5) & 7;
    int q    = i >> 8;            // tap*4 + ks
    int ks   = q & 3;
    int tap  = q >> 2;
    int kh = tap / 3, kw = tap - kh * 3;

    int r  = lane >> 2;
    int k0 = ks * 16 + (lane & 3) * 2;

    uint32_t words[4];
#pragma unroll
    for (int wi = 0; wi < 4; wi++) {
        int co = mblk * 16 + r + (wi & 1) * 8;
        int kk = k0 + (wi >> 1) * 8;
        uint32_t packed = 0;
#pragma unroll
        for (int j = 0; j < 2; j++) {
            float v = w[((co * CIN + (kk + j)) * 3 + kh) * 3 + kw];
            packed |= (uint32_t)__half_as_ushort(__float2half(v)) << (16 * j);
        }
        words[wi] = packed;
    }
    g_Wfrag[i] = make_uint4(words[0], words[1], words[2], words[3]);
}

// ---- transpose+convert: x[b][ci][y][px] fp32 -> g_xh[b][y][px][ci] fp16 ----
#define TSTR 72   // smem half-stride per px row (144B, 16B-aligned)
__global__ __launch_bounds__(256)
void prep_x(const float* __restrict__ x) {
    __shared__ __half sT[64 * TSTR];   // [px(64)][ci(64)] halfs
    const int b   = blockIdx.z;
    const int y   = blockIdx.y;
    const int px0 = blockIdx.x * 64;
    const int t   = threadIdx.x;
    const int wid = t >> 5, lane = t & 31;

    const int px = (wid & 1) * 32 + lane;
    const int ip = px0 + px;
    const bool okx = ip < WW;
    const int cib = wid >> 1;          // 0..3
#pragma unroll
    for (int k = 0; k < 16; k++) {
        int ci = cib + k * 4;
        float v = okx ? __ldg(&x[(((size_t)b * CIN + ci) * HH + y) * WW + ip]) : 0.0f;
        sT[px * TSTR + ci] = __float2half(v);
    }
    __syncthreads();

    for (int c = t; c < 512; c += 256) {      // 64 px * 8 cig chunks of 16B
        int pxw = c >> 3, cig = c & 7;
        int ipw = px0 + pxw;
        if (ipw < WW) {
            uint4 val = *(const uint4*)&sT[pxw * TSTR + cig * 8];
            *(uint4*)((char*)g_xh + (((size_t)(b * HH + y) * WW + ipw) << 7) + (cig << 4)) = val;
        }
    }
}

// ---------------- helpers ----------------
__device__ __forceinline__ uint32_t smem_u32(const void* p) {
    uint32_t a;
    asm("{ .reg .u64 t; cvta.to.shared.u64 t, %1; cvt.u32.u64 %0, t; }" : "=r"(a) : "l"(p));
    return a;
}
__device__ __forceinline__ uint32_t swz(uint32_t off) { return off ^ ((off >> 3) & 0x70); }

__device__ __forceinline__ void ldsm4(uint32_t& r0, uint32_t& r1, uint32_t& r2, uint32_t& r3, uint32_t addr) {
    asm volatile("ldmatrix.sync.aligned.m8n8.x4.shared.b16 {%0, %1, %2, %3}, [%4];"
        : "=r"(r0), "=r"(r1), "=r"(r2), "=r"(r3) : "r"(addr));
}
__device__ __forceinline__ void mma16816(float* d, const uint4& a, uint32_t b0, uint32_t b1) {
    asm volatile("mma.sync.aligned.m16n8k16.row.col.f32.f16.f16.f32 "
        "{%0, %1, %2, %3}, {%4, %5, %6, %7}, {%8, %9}, {%0, %1, %2, %3};"
        : "+f"(d[0]), "+f"(d[1]), "+f"(d[2]), "+f"(d[3])
        : "r"(a.x), "r"(a.y), "r"(a.z), "r"(a.w), "r"(b0), "r"(b1));
}
__device__ __forceinline__ void cp16(uint32_t dst, const void* src, int sz) {
    asm volatile("cp.async.cg.shared.global [%0], [%1], 16, %2;"
        :: "r"(dst), "l"(src), "r"(sz) : "memory");
}

#define OFF_MIN (INROWS * SLAB_STRIDE)            // 30720
#define SMEM_BYTES (OFF_MIN + 1024 + 1024)        // slabs + sMin + align slack

__global__ __launch_bounds__(256, 2)
void conv_mma_kernel(const float* __restrict__ bias,
                     float* __restrict__ out) {
    extern __shared__ char smem_raw[];
    uint32_t sb = (smem_u32(smem_raw) + 1023u) & ~1023u;

    const int tid  = threadIdx.x;
    const int wid  = tid >> 5;
    const int lane = tid & 31;
    const int b    = blockIdx.z;
    const int oy0  = blockIdx.y * TROWS;
    const int x0   = blockIdx.x * TPX;

    const int warpM = wid & 1;       // co half: 64*warpM .. +63
    const int warpN = wid >> 1;      // output row within tile: 0..3

    // ---- async-stage slabs: [irow(6)][px(34)][64 ci fp16], SW128 swizzle ----
    for (int g = 0; g < INROWS; g++) {
        int y = oy0 + g;
#pragma unroll 1
        for (int c = tid; c < PXST * 8; c += 256) {
            int px  = c >> 3;
            int cig = c & 7;
            int ix  = x0 + px;
            bool ok = (y < HH) && (ix < WW);
            const char* src = (const char*)g_xh +
                (ok ? ((((size_t)(b * HH + y) * WW + ix) << 7) + ((size_t)cig << 4)) : 0);
            uint32_t dst = sb + (uint32_t)(g * SLAB_STRIDE)
                         + (uint32_t)(px * 128 + ((cig ^ (px & 7)) << 4));
            cp16(dst, src, ok ? 16 : 0);
        }
        asm volatile("cp.async.commit_group;" ::: "memory");
    }

    // ---- accumulators init 0; bias folded into epilogue ----
    float acc[4][4][4];
#pragma unroll
    for (int m = 0; m < 4; m++)
#pragma unroll
        for (int f = 0; f < 4; f++) {
            acc[m][f][0] = 0.f; acc[m][f][1] = 0.f;
            acc[m][f][2] = 0.f; acc[m][f][3] = 0.f;
        }

    const uint4* gw = g_Wfrag;
    const int rowpx   = (lane & 7) + ((lane >> 4) << 3);   // 0..15
    const int kb_lane = ((lane >> 3) & 1) * 16;
    const int awoff   = warpM * 4;

#pragma unroll
    for (int kh = 0; kh < 3; kh++) {
        if (kh == 0)      asm volatile("cp.async.wait_group 2;" ::: "memory");
        else if (kh == 1) asm volatile("cp.async.wait_group 1;" ::: "memory");
        else              asm volatile("cp.async.wait_group 0;" ::: "memory");
        __syncthreads();

        const uint32_t slab = sb + (uint32_t)((warpN + kh) * SLAB_STRIDE);

        // 2-deep software pipeline over flattened (kw,ks): it = kw*4 + ks
        uint4    A[2][4];
        uint32_t B[2][8];

        // prime it=0 (kw=0, ks=0)
        {
            const int base = (kh * 3 * 4) * 8;    // tap=kh*3, ks=0
#pragma unroll
            for (int m = 0; m < 4; m++)
                A[0][m] = __ldg(&gw[(base + awoff + m) * 32 + lane]);
#pragma unroll
            for (int half = 0; half < 2; half++) {
                uint32_t off = swz((uint32_t)((rowpx + half * 16) * 128 + kb_lane));
                ldsm4(B[0][half*4+0], B[0][half*4+1], B[0][half*4+2], B[0][half*4+3], slab + off);
            }
        }

#pragma unroll
        for (int it = 0; it < 12; it++) {
            const int cur = it & 1, nxt = cur ^ 1;
            if (it < 11) {
                const int itn = it + 1;
                const int kwn = itn >> 2, ksn = itn & 3;
                const int base = ((kh * 3 + kwn) * 4 + ksn) * 8;
#pragma unroll
                for (int m = 0; m < 4; m++)
                    A[nxt][m] = __ldg(&gw[(base + awoff + m) * 32 + lane]);
#pragma unroll
                for (int half = 0; half < 2; half++) {
                    uint32_t off = swz((uint32_t)((rowpx + half * 16 + kwn) * 128 + kb_lane + ksn * 32));
                    ldsm4(B[nxt][half*4+0], B[nxt][half*4+1], B[nxt][half*4+2], B[nxt][half*4+3], slab + off);
                }
            }
#pragma unroll
            for (int m = 0; m < 4; m++) {
#pragma unroll
                for (int f = 0; f < 4; f++)
                    mma16816(acc[m][f], A[cur][m], B[cur][f*2], B[cur][f*2+1]);
            }
        }
    }

    // ---- epilogue: add bias, min over co ----
    float* sMin = (float*)(smem_raw + (sb - smem_u32(smem_raw)) + OFF_MIN);  // [2][128]

    float bias0[4], bias1[4];
#pragma unroll
    for (int m = 0; m < 4; m++) {
        int r_co = warpM * 64 + m * 16 + (lane >> 2);
        bias0[m] = __ldg(&bias[r_co]);
        bias1[m] = __ldg(&bias[r_co + 8]);
    }

#pragma unroll
    for (int f = 0; f < 4; f++) {
        float v0 = __int_as_float(0x7f800000), v1 = v0;
#pragma unroll
        for (int m = 0; m < 4; m++) {
            v0 = fminf(v0, fminf(acc[m][f][0] + bias0[m], acc[m][f][2] + bias1[m]));
            v1 = fminf(v1, fminf(acc[m][f][1] + bias0[m], acc[m][f][3] + bias1[m]));
        }
#pragma unroll
        for (int off = 4; off < 32; off <<= 1) {
            v0 = fminf(v0, __shfl_xor_sync(0xffffffffu, v0, off));
            v1 = fminf(v1, __shfl_xor_sync(0xffffffffu, v1, off));
        }
        if ((lane >> 2) == 0) {
            int px = (f >> 1) * 16 + (f & 1) * 8 + (lane & 3) * 2;  // 0..31 within row
            int idx = warpN * TPX + px;
            sMin[warpM * 128 + idx]     = v0;
            sMin[warpM * 128 + idx + 1] = v1;
        }
    }
    __syncthreads();

    if (tid < 128) {
        int r = tid >> 5, c = tid & 31;
        int orow = oy0 + r, ocol = x0 + c;
        if (orow < OH && ocol < OW) {
            float m = fminf(sMin[tid], sMin[128 + tid]);
            out[((size_t)b * OH + orow) * OW + ocol] = tanhf(tanhf(m));
        }
    }
}

extern "C" void kernel_launch(void* const* d_in, const int* in_sizes, int n_in,
                              void* d_out, int out_size) {
    const float* x    = (const float*)d_in[0];
    const float* w    = (const float*)d_in[1];
    const float* bias = (const float*)d_in[2];
    float* out = (float*)d_out;

    prep_w<<<(9216 + 255) / 256, 256>>>(w);
    prep_x<<<dim3(4, HH, 16), 256>>>(x);

    cudaFuncSetAttribute(conv_mma_kernel, cudaFuncAttributeMaxDynamicSharedMemorySize, SMEM_BYTES);
    dim3 grid((OW + TPX - 1) / TPX,      // 7
              (OH + TROWS - 1) / TROWS,  // 56
              16);
    conv_mma_kernel<<<grid, 256, SMEM_BYTES>>>(bias, out);
}

// round 10
// speedup vs baseline: 1.1164x; 1.0517x over previous
#include <cuda_runtime.h>
#include <cuda_fp16.h>
#include <cstdint>
#include <math.h>

#define CIN   64
#define COUT  128
#define HH    224
#define WW    224
#define OH    222
#define OW    222

#define TPX    16          // output px per tile (x)
#define TROWS  8           // output rows per tile (y)
#define INROWS 10          // staged input rows = TROWS + 2
#define PXST   18          // staged px per row = TPX + 2
#define SLAB_STRIDE 3072   // bytes per input row slab (px padded to 24; mult of 1024)

// ---------------- global scratch ----------------
// fp16 transposed input: [b][y][px][ci], 16*224*224*64 halfs (~103MB)
__device__ __half g_xh[(size_t)16 * HH * WW * CIN];
// a-fragment-shuffled fp16 weights: [tap(9)][ks(4)][mblk(8)][lane(32)] x uint4
__device__ uint4 g_Wfrag[9 * 4 * 8 * 32];

// ---- fused prep: weight shuffle (9 blocks) + x transpose/convert ----
#define TSTR 72   // smem half-stride per px row (144B, 16B-aligned)
__global__ __launch_bounds__(256)
void prep_all(const float* __restrict__ x, const float* __restrict__ w) {
    __shared__ __half sT[64 * TSTR];   // [px(64)][ci(64)] halfs
    const int b   = blockIdx.z;
    const int y   = blockIdx.y;
    const int px0 = blockIdx.x * 64;
    const int t   = threadIdx.x;
    const int wid = t >> 5, lane = t & 31;

    // --- weight shuffle piggybacked on 9 blocks (b==0, x==0, y<9) ---
    if (b == 0 && blockIdx.x == 0 && y < 9) {
#pragma unroll
        for (int rep = 0; rep < 4; rep++) {
            int i = (y * 4 + rep) * 256 + t;    // 0..9215
            int ln   = i & 31;
            int mblk = (i >> 5) & 7;
            int q    = i >> 8;            // tap*4 + ks
            int ks   = q & 3;
            int tap  = q >> 2;
            int kh = tap / 3, kw = tap - kh * 3;
            int r  = ln >> 2;
            int k0 = ks * 16 + (ln & 3) * 2;
            uint32_t words[4];
#pragma unroll
            for (int wi = 0; wi < 4; wi++) {
                int co = mblk * 16 + r + (wi & 1) * 8;
                int kk = k0 + (wi >> 1) * 8;
                uint32_t packed = 0;
#pragma unroll
                for (int j = 0; j < 2; j++) {
                    float v = w[((co * CIN + (kk + j)) * 3 + kh) * 3 + kw];
                    packed |= (uint32_t)__half_as_ushort(__float2half(v)) << (16 * j);
                }
                words[wi] = packed;
            }
            g_Wfrag[i] = make_uint4(words[0], words[1], words[2], words[3]);
        }
    }

    // --- x transpose/convert ---
    const int px = (wid & 1) * 32 + lane;
    const int ip = px0 + px;
    const bool okx = ip < WW;
    const int cib = wid >> 1;          // 0..3
#pragma unroll
    for (int k = 0; k < 16; k++) {
        int ci = cib + k * 4;
        float v = okx ? __ldg(&x[(((size_t)b * CIN + ci) * HH + y) * WW + ip]) : 0.0f;
        sT[px * TSTR + ci] = __float2half(v);
    }
    __syncthreads();

    for (int c = t; c < 512; c += 256) {      // 64 px * 8 cig chunks of 16B
        int pxw = c >> 3, cig = c & 7;
        int ipw = px0 + pxw;
        if (ipw < WW) {
            uint4 val = *(const uint4*)&sT[pxw * TSTR + cig * 8];
            *(uint4*)((char*)g_xh + (((size_t)(b * HH + y) * WW + ipw) << 7) + (cig << 4)) = val;
        }
    }
}

// ---------------- helpers ----------------
__device__ __forceinline__ uint32_t smem_u32(const void* p) {
    uint32_t a;
    asm("{ .reg .u64 t; cvta.to.shared.u64 t, %1; cvt.u32.u64 %0, t; }" : "=r"(a) : "l"(p));
    return a;
}
__device__ __forceinline__ uint32_t swz(uint32_t off) { return off ^ ((off >> 3) & 0x70); }

__device__ __forceinline__ void ldsm4(uint32_t& r0, uint32_t& r1, uint32_t& r2, uint32_t& r3, uint32_t addr) {
    asm volatile("ldmatrix.sync.aligned.m8n8.x4.shared.b16 {%0, %1, %2, %3}, [%4];"
        : "=r"(r0), "=r"(r1), "=r"(r2), "=r"(r3) : "r"(addr));
}
__device__ __forceinline__ void mma16816(float* d, const uint4& a, uint32_t b0, uint32_t b1) {
    asm volatile("mma.sync.aligned.m16n8k16.row.col.f32.f16.f16.f32 "
        "{%0, %1, %2, %3}, {%4, %5, %6, %7}, {%8, %9}, {%0, %1, %2, %3};"
        : "+f"(d[0]), "+f"(d[1]), "+f"(d[2]), "+f"(d[3])
        : "r"(a.x), "r"(a.y), "r"(a.z), "r"(a.w), "r"(b0), "r"(b1));
}
__device__ __forceinline__ void cp16(uint32_t dst, const void* src, int sz) {
    asm volatile("cp.async.cg.shared.global [%0], [%1], 16, %2;"
        :: "r"(dst), "l"(src), "r"(sz) : "memory");
}

#define OFF_MIN (INROWS * SLAB_STRIDE)            // 30720
#define SMEM_BYTES (OFF_MIN + 1024 + 1024)

__global__ __launch_bounds__(256, 2)
void conv_mma_kernel(const float* __restrict__ bias,
                     float* __restrict__ out) {
    extern __shared__ char smem_raw[];
    uint32_t sb = (smem_u32(smem_raw) + 1023u) & ~1023u;

    const int tid  = threadIdx.x;
    const int wid  = tid >> 5;
    const int lane = tid & 31;
    const int b    = blockIdx.z;
    const int oy0  = blockIdx.y * TROWS;
    const int x0   = blockIdx.x * TPX;

    const int warpM = wid & 1;       // co half: 64*warpM .. +63
    const int warpN = wid >> 1;      // output row pair: rows 2*warpN, 2*warpN+1

    // ---- async-stage slabs: [irow(10)][px(18)][64 ci fp16], SW128 swizzle ----
    for (int g = 0; g < INROWS; g++) {
        int y = oy0 + g;
#pragma unroll 1
        for (int c = tid; c < PXST * 8; c += 256) {   // 144 chunks
            int px  = c >> 3;
            int cig = c & 7;
            int ix  = x0 + px;
            bool ok = (y < HH) && (ix < WW);
            const char* src = (const char*)g_xh +
                (ok ? ((((size_t)(b * HH + y) * WW + ix) << 7) + ((size_t)cig << 4)) : 0);
            uint32_t dst = sb + (uint32_t)(g * SLAB_STRIDE)
                         + (uint32_t)(px * 128 + ((cig ^ (px & 7)) << 4));
            cp16(dst, src, ok ? 16 : 0);
        }
        asm volatile("cp.async.commit_group;" ::: "memory");
    }

    // ---- accumulators, init = bias[co] ----
    float acc[4][4][4];
#pragma unroll
    for (int m = 0; m < 4; m++) {
        int r_co = warpM * 64 + m * 16 + (lane >> 2);
        float b0 = __ldg(&bias[r_co]);
        float b1 = __ldg(&bias[r_co + 8]);
#pragma unroll
        for (int f = 0; f < 4; f++) {
            acc[m][f][0] = b0; acc[m][f][1] = b0;
            acc[m][f][2] = b1; acc[m][f][3] = b1;
        }
    }

    const uint4* gw = g_Wfrag;
    // ldsm per-lane addressing: px-within-row and k-half column
    const int pxl     = lane & 7;                  // px row within frag pair
    const int fhalf   = (lane >> 4) & 1;           // 0: f even uses px 0-7, 1: px 8-15
    const int kb_lane = ((lane >> 3) & 1) * 16;    // 16B column = second 8-ci half
    const int awoff   = warpM * 4;

#pragma unroll
    for (int kh = 0; kh < 3; kh++) {
        if (kh == 0)      asm volatile("cp.async.wait_group 2;" ::: "memory");
        else if (kh == 1) asm volatile("cp.async.wait_group 1;" ::: "memory");
        else              asm volatile("cp.async.wait_group 0;" ::: "memory");
        __syncthreads();

        const uint32_t row0 = sb + (uint32_t)((2 * warpN + kh) * SLAB_STRIDE);
#pragma unroll
        for (int kw = 0; kw < 3; kw++) {
            const int tap = kh * 3 + kw;
#pragma unroll
            for (int ks = 0; ks < 4; ks++) {
                uint4 A[4];
                const int base = (tap * 4 + ks) * 8;
#pragma unroll
                for (int m = 0; m < 4; m++)
                    A[m] = __ldg(&gw[(base + awoff + m) * 32 + lane]);

                // B frags: half h covers output row 2*warpN+h; f pairs (h*2, h*2+1)
                uint32_t B[8];
#pragma unroll
                for (int h = 0; h < 2; h++) {
                    uint32_t off = swz((uint32_t)((pxl + fhalf * 8 + kw) * 128 + kb_lane + ks * 32));
                    ldsm4(B[h*4+0], B[h*4+1], B[h*4+2], B[h*4+3],
                          row0 + (uint32_t)(h * SLAB_STRIDE) + off);
                }
#pragma unroll
                for (int m = 0; m < 4; m++) {
#pragma unroll
                    for (int f = 0; f < 4; f++)
                        mma16816(acc[m][f], A[m], B[f*2], B[f*2+1]);
                }
            }
        }
    }

    // ---- epilogue: min over co ----
    float* sMin = (float*)(smem_raw + (sb - smem_u32(smem_raw)) + OFF_MIN);  // [2][128]

#pragma unroll
    for (int f = 0; f < 4; f++) {
        float v0 = __int_as_float(0x7f800000), v1 = v0;
#pragma unroll
        for (int m = 0; m < 4; m++) {
            v0 = fminf(v0, fminf(acc[m][f][0], acc[m][f][2]));
            v1 = fminf(v1, fminf(acc[m][f][1], acc[m][f][3]));
        }
#pragma unroll
        for (int off = 4; off < 32; off <<= 1) {
            v0 = fminf(v0, __shfl_xor_sync(0xffffffffu, v0, off));
            v1 = fminf(v1, __shfl_xor_sync(0xffffffffu, v1, off));
        }
        if ((lane >> 2) == 0) {
            // f -> (row within pair = f>>1, px group = f&1)
            int r_loc = 2 * warpN + (f >> 1);
            int px    = (f & 1) * 8 + (lane & 3) * 2;
            int idx   = r_loc * TPX + px;
            sMin[warpM * 128 + idx]     = v0;
            sMin[warpM * 128 + idx + 1] = v1;
        }
    }
    __syncthreads();

    if (tid < 128) {
        int r = tid >> 4, c = tid & 15;
        int orow = oy0 + r, ocol = x0 + c;
        if (orow < OH && ocol < OW) {
            float m = fminf(sMin[tid], sMin[128 + tid]);
            out[((size_t)b * OH + orow) * OW + ocol] = tanhf(tanhf(m));
        }
    }
}

extern "C" void kernel_launch(void* const* d_in, const int* in_sizes, int n_in,
                              void* d_out, int out_size) {
    const float* x    = (const float*)d_in[0];
    const float* w    = (const float*)d_in[1];
    const float* bias = (const float*)d_in[2];
    float* out = (float*)d_out;

    prep_all<<<dim3(4, HH, 16), 256>>>(x, w);

    cudaFuncSetAttribute(conv_mma_kernel, cudaFuncAttributeMaxDynamicSharedMemorySize, SMEM_BYTES);
    dim3 grid((OW + TPX - 1) / TPX,      // 14
              (OH + TROWS - 1) / TROWS,  // 28
              16);
    conv_mma_kernel<<<grid, 256, SMEM_BYTES>>>(bias, out);
}